// round 5
// baseline (speedup 1.0000x reference)
#include <cuda_runtime.h>
#include <cmath>

#define NMAX 20000

__device__ float g_PHI[NMAX * 32];
__device__ float g_ENV[NMAX];
__device__ float g_F[NMAX * 192];

// ---------------------------------------------------------------------------
// Edge kernel: scatter env-weighted RBF vector + env into per-node sums.
// ---------------------------------------------------------------------------
__global__ void edge_kernel(const float* __restrict__ dist,
                            const int* __restrict__ nb, int E,
                            float mu0, float delta, float inv_delta,
                            float beta, float c2, float q)
{
    int e = blockIdx.x * blockDim.x + threadIdx.x;
    if (e >= E) return;
    float d = dist[e];
    int j = nb[e];
    float env = 0.0f;
    if (d < 5.0f) env = 0.5f * (__cosf(0.62831853071795864769f * d) + 1.0f);
    atomicAdd(&g_ENV[j], env);

    float t = __expf(-d);
    int r0 = (int)floorf((t - mu0) * inv_delta + 0.5f);
    r0 = max(0, min(31, r0));
    float u0 = t - (mu0 + delta * (float)r0);
    float p0 = env * __expf(-beta * u0 * u0);
    float* phr = g_PHI + (size_t)j * 32;
    const float THR = 1e-6f;
    if (p0 > THR) atomicAdd(&phr[r0], p0);

    float w = __expf(c2 * (t - (mu0 + delta * ((float)r0 + 0.5f))));
    float p = p0;
    for (int r = r0 + 1; r < 32; ++r) {
        p *= w; w *= q;
        if (p <= THR) break;
        atomicAdd(&phr[r], p);
    }
    w = __expf(-c2 * (t - (mu0 + delta * ((float)r0 - 0.5f))));
    p = p0;
    for (int r = r0 - 1; r >= 0; --r) {
        p *= w; w *= q;
        if (p <= THR) break;
        atomicAdd(&phr[r], p);
    }
}

// ---------------------------------------------------------------------------
// Coefficient kernel: F[n, o] = env[n]*bd[o] + sum_r Wd[o, r] * phi[n, r]
// One block (192 threads) per node.
// ---------------------------------------------------------------------------
__global__ void coeff_kernel(const float* __restrict__ Wd,
                             const float* __restrict__ bd, int N)
{
    __shared__ float ph[32];
    int n = blockIdx.x;
    int o = threadIdx.x;
    if (o < 32) ph[o] = g_PHI[(size_t)n * 32 + o];
    __syncthreads();
    float acc = g_ENV[n] * bd[o];
    const float4* w = (const float4*)(Wd + (size_t)o * 32);
    #pragma unroll
    for (int r4 = 0; r4 < 8; ++r4) {
        float4 wv = w[r4];
        acc += wv.x * ph[4 * r4] + wv.y * ph[4 * r4 + 1]
             + wv.z * ph[4 * r4 + 2] + wv.w * ph[4 * r4 + 3];
    }
    g_F[(size_t)n * 192 + o] = acc;
}

// ---------------------------------------------------------------------------
// f32x2 packed FMA helpers
// ---------------------------------------------------------------------------
__device__ __forceinline__ void ffma2(unsigned long long& d,
                                      unsigned long long a,
                                      unsigned long long b)
{
    asm("fma.rn.f32x2 %0, %1, %2, %0;" : "+l"(d) : "l"(a), "l"(b));
}
__device__ __forceinline__ float sum2(unsigned long long v)
{
    float lo, hi;
    asm("mov.b64 {%0, %1}, %2;" : "=f"(lo), "=f"(hi) : "l"(v));
    return lo + hi;
}

__device__ __forceinline__ void decomp9(const float x[9], float* iso,
                                        float a[3], float s[5])
{
    float m = (x[0] + x[4] + x[8]) * (1.0f / 3.0f);
    *iso = m;
    a[0] = 0.5f * (x[1] - x[3]);
    a[1] = 0.5f * (x[2] - x[6]);
    a[2] = 0.5f * (x[5] - x[7]);
    s[0] = x[0] - m;
    s[1] = 0.5f * (x[1] + x[3]);
    s[2] = 0.5f * (x[2] + x[6]);
    s[3] = x[4] - m;
    s[4] = 0.5f * (x[5] + x[7]);
}

__device__ __forceinline__ void build9(float iso, const float a[3],
                                       const float s[5], float Y[9])
{
    Y[0] = iso + s[0];        Y[1] = a[0] + s[1];       Y[2] = a[1] + s[2];
    Y[3] = s[1] - a[0];       Y[4] = iso + s[3];        Y[5] = a[2] + s[4];
    Y[6] = s[2] - a[1];       Y[7] = s[4] - a[2];       Y[8] = iso - s[0] - s[3];
}

// ---------------------------------------------------------------------------
// Node kernel layout: 16 warps/block, 2 nodes/warp per iteration.
// Weights: 6 matrices, rows padded to WROW=68 (LDS.128 conflict-free).
// Comp rows per node: 32 rows x 20 floats (16B aligned):
//   row j = [m0(2j) m0(2j+1) m1 pair ... m8 pair] ; m0=iso, m1-3=A, m4-8=S.
// ---------------------------------------------------------------------------
#define NWARP 16
#define WROW 68
#define CPSZ 640                   // 32 rows * 20 floats (per node)
#define OFF_W    0                 // 6 * 64 * 68 = 26112
#define OFF_WARP 26112
#define WSZ      1864              // 2*CPSZ (1280) + xs 576 + pad 8
#define SMEM_FLOATS (OFF_WARP + NWARP * WSZ)   // 55936 floats = 223,744 B

// pass 1: iso + antisym (m0..m3), NC accs: I:[2][2], A:[3][2][2]
__device__ __forceinline__ void pass_IA(const float* __restrict__ WI,
                                        const float* __restrict__ WA,
                                        const float* __restrict__ cp,
                                        int lane,
                                        unsigned long long accI[2][2],
                                        unsigned long long accA[3][2][2])
{
    const float* wI0 = WI + lane * WROW;
    const float* wI1 = WI + (lane + 32) * WROW;
    const float* wA0 = WA + lane * WROW;
    const float* wA1 = WA + (lane + 32) * WROW;
    #pragma unroll 4
    for (int jj = 0; jj < 16; ++jj) {
        ulonglong2 vI0 = *(const ulonglong2*)(wI0 + 4 * jj);
        ulonglong2 vI1 = *(const ulonglong2*)(wI1 + 4 * jj);
        ulonglong2 vA0 = *(const ulonglong2*)(wA0 + 4 * jj);
        ulonglong2 vA1 = *(const ulonglong2*)(wA1 + 4 * jj);
        #pragma unroll
        for (int t = 0; t < 2; ++t) {
            unsigned long long wi0 = t ? vI0.y : vI0.x;
            unsigned long long wi1 = t ? vI1.y : vI1.x;
            unsigned long long wa0 = t ? vA0.y : vA0.x;
            unsigned long long wa1 = t ? vA1.y : vA1.x;
            int j = 2 * jj + t;
            #pragma unroll
            for (int n = 0; n < 2; ++n) {
                const float* row = cp + n * CPSZ + j * 20;
                ulonglong2 q0 = *(const ulonglong2*)(row);       // m0, m1
                ulonglong2 q1 = *(const ulonglong2*)(row + 4);   // m2, m3
                ffma2(accI[0][n], wi0, q0.x);
                ffma2(accI[1][n], wi1, q0.x);
                ffma2(accA[0][0][n], wa0, q0.y);
                ffma2(accA[1][0][n], wa0, q1.x);
                ffma2(accA[2][0][n], wa0, q1.y);
                ffma2(accA[0][1][n], wa1, q0.y);
                ffma2(accA[1][1][n], wa1, q1.x);
                ffma2(accA[2][1][n], wa1, q1.y);
            }
        }
    }
}

// pass 2: traceless-sym (m4..m8), accs S:[5][2][2]
__device__ __forceinline__ void pass_S(const float* __restrict__ WS,
                                       const float* __restrict__ cp,
                                       int lane,
                                       unsigned long long accS[5][2][2])
{
    const float* wS0 = WS + lane * WROW;
    const float* wS1 = WS + (lane + 32) * WROW;
    #pragma unroll 4
    for (int jj = 0; jj < 16; ++jj) {
        ulonglong2 vS0 = *(const ulonglong2*)(wS0 + 4 * jj);
        ulonglong2 vS1 = *(const ulonglong2*)(wS1 + 4 * jj);
        #pragma unroll
        for (int t = 0; t < 2; ++t) {
            unsigned long long ws0 = t ? vS0.y : vS0.x;
            unsigned long long ws1 = t ? vS1.y : vS1.x;
            int j = 2 * jj + t;
            #pragma unroll
            for (int n = 0; n < 2; ++n) {
                const float* row = cp + n * CPSZ + j * 20;
                ulonglong2 q2 = *(const ulonglong2*)(row + 8);    // m4, m5
                ulonglong2 q3 = *(const ulonglong2*)(row + 12);   // m6, m7
                unsigned long long m8 = *(const unsigned long long*)(row + 16);
                ffma2(accS[0][0][n], ws0, q2.x);
                ffma2(accS[1][0][n], ws0, q2.y);
                ffma2(accS[2][0][n], ws0, q3.x);
                ffma2(accS[3][0][n], ws0, q3.y);
                ffma2(accS[4][0][n], ws0, m8);
                ffma2(accS[0][1][n], ws1, q2.x);
                ffma2(accS[1][1][n], ws1, q2.y);
                ffma2(accS[2][1][n], ws1, q3.x);
                ffma2(accS[3][1][n], ws1, q3.y);
                ffma2(accS[4][1][n], ws1, m8);
            }
        }
    }
}

__global__ __launch_bounds__(512, 1)
void node_kernel(const float* __restrict__ X,
    const float* __restrict__ WIa, const float* __restrict__ WAa, const float* __restrict__ WSa,
    const float* __restrict__ WIb, const float* __restrict__ WAb, const float* __restrict__ WSb,
    float* __restrict__ out, int N)
{
    extern __shared__ float sm[];
    int tid  = threadIdx.x;
    int warp = tid >> 5;
    int lane = tid & 31;

    // ---- stage weights (once per block) ----
    {
        const float* Ws[6] = {WIa, WAa, WSa, WIb, WAb, WSb};
        #pragma unroll
        for (int m = 0; m < 6; ++m) {
            const float* src = Ws[m];
            float* dst = sm + OFF_W + m * (64 * WROW);
            for (int idx = tid; idx < 4096; idx += 512)
                dst[(idx >> 6) * WROW + (idx & 63)] = src[idx];
        }
    }
    __syncthreads();

    float* cp = sm + OFF_WARP + warp * WSZ;   // 2 * 640
    float* xs = cp + 2 * CPSZ;                 // 576

    const float* smWI_a = sm + OFF_W + 0 * (64 * WROW);
    const float* smWA_a = sm + OFF_W + 1 * (64 * WROW);
    const float* smWS_a = sm + OFF_W + 2 * (64 * WROW);
    const float* smWI_b = sm + OFF_W + 3 * (64 * WROW);
    const float* smWA_b = sm + OFF_W + 4 * (64 * WROW);
    const float* smWS_b = sm + OFF_W + 5 * (64 * WROW);

    int Q = (N + 1) >> 1;
    int gw = blockIdx.x * NWARP + warp;
    int step = gridDim.x * NWARP;

    for (int q = gw; q < Q; q += step) {
        int n0 = q << 1;

        // ---- per-node: stage X, normalize, decompose -> comp rows ----
        #pragma unroll
        for (int n = 0; n < 2; ++n) {
            int node = n0 + n;
            if (node < N) {
                const float4* src = (const float4*)(X + (size_t)node * 576);
                float4* dst = (float4*)xs;
                #pragma unroll
                for (int i = 0; i < 5; ++i) {
                    int idx = lane + 32 * i;
                    if (idx < 144) dst[idx] = src[idx];
                }
            }
            __syncwarp();
            float* cpn = cp + n * CPSZ;
            #pragma unroll
            for (int h = 0; h < 2; ++h) {
                int c = lane + 32 * h;
                float x[9];
                #pragma unroll
                for (int k = 0; k < 9; ++k) x[k] = xs[c * 9 + k];
                float f = 0.0f;
                #pragma unroll
                for (int k = 0; k < 9; ++k) f += x[k] * x[k];
                float sc = __fdividef(1.0f, f + 1.0f);
                #pragma unroll
                for (int k = 0; k < 9; ++k) x[k] *= sc;
                float iso, a[3], s[5];
                decomp9(x, &iso, a, s);
                float* row = cpn + (c >> 1) * 20 + (c & 1);
                row[0]  = iso;
                row[2]  = a[0]; row[4]  = a[1]; row[6]  = a[2];
                row[8]  = s[0]; row[10] = s[1]; row[12] = s[2];
                row[14] = s[3]; row[16] = s[4];
            }
            __syncwarp();
        }

        // ---- load coefficients F ----
        float fI[2][2], fA[2][2], fS[2][2];
        #pragma unroll
        for (int n = 0; n < 2; ++n) {
            int node = min(n0 + n, N - 1);
            const float* Fn = g_F + (size_t)node * 192;
            #pragma unroll
            for (int h = 0; h < 2; ++h) {
                int c = lane + 32 * h;
                fI[h][n] = Fn[c];
                fA[h][n] = Fn[64 + c];
                fS[h][n] = Fn[128 + c];
            }
        }

        // ---- pre mixes ----
        float yi[2][2], ya[3][2][2], ys[5][2][2];
        {
            unsigned long long accI[2][2] = {};
            unsigned long long accA[3][2][2] = {};
            pass_IA(smWI_a, smWA_a, cp, lane, accI, accA);
            #pragma unroll
            for (int h = 0; h < 2; ++h)
                #pragma unroll
                for (int n = 0; n < 2; ++n) {
                    yi[h][n] = sum2(accI[h][n]);
                    #pragma unroll
                    for (int k = 0; k < 3; ++k) ya[k][h][n] = sum2(accA[k][h][n]);
                }
        }
        {
            unsigned long long accS[5][2][2] = {};
            pass_S(smWS_a, cp, lane, accS);
            #pragma unroll
            for (int h = 0; h < 2; ++h)
                #pragma unroll
                for (int n = 0; n < 2; ++n)
                    #pragma unroll
                    for (int k = 0; k < 5; ++k) ys[k][h][n] = sum2(accS[k][h][n]);
        }

        // ---- sandwich: Z = YM + MY, normalize, decompose -> overwrite comps
        // (each lane reads/writes only its own channels: no cross-lane hazard)
        #pragma unroll
        for (int n = 0; n < 2; ++n) {
            float* cpn = cp + n * CPSZ;
            #pragma unroll
            for (int h = 0; h < 2; ++h) {
                int c = lane + 32 * h;
                float* row = cpn + (c >> 1) * 20 + (c & 1);
                float Y[9], M[9];
                float av[3] = {ya[0][h][n], ya[1][h][n], ya[2][h][n]};
                float sv[5] = {ys[0][h][n], ys[1][h][n], ys[2][h][n],
                               ys[3][h][n], ys[4][h][n]};
                build9(yi[h][n], av, sv, Y);
                float mi = fI[h][n] * row[0];
                float A[3] = {fA[h][n] * row[2], fA[h][n] * row[4],
                              fA[h][n] * row[6]};
                float S[5] = {fS[h][n] * row[8],  fS[h][n] * row[10],
                              fS[h][n] * row[12], fS[h][n] * row[14],
                              fS[h][n] * row[16]};
                build9(mi, A, S, M);
                float Z[9];
                #pragma unroll
                for (int i = 0; i < 3; ++i)
                    #pragma unroll
                    for (int jj = 0; jj < 3; ++jj) {
                        float acc = 0.0f;
                        #pragma unroll
                        for (int k = 0; k < 3; ++k)
                            acc += Y[i * 3 + k] * M[k * 3 + jj]
                                 + M[i * 3 + k] * Y[k * 3 + jj];
                        Z[i * 3 + jj] = acc;
                    }
                float nrm = 0.0f;
                #pragma unroll
                for (int k = 0; k < 9; ++k) { float v = Z[k] + 1.0f; nrm += v * v; }
                float inv = __fdividef(1.0f, nrm);
                #pragma unroll
                for (int k = 0; k < 9; ++k) Z[k] *= inv;
                float iso, a2[3], s2[5];
                decomp9(Z, &iso, a2, s2);
                row[0]  = iso;
                row[2]  = a2[0]; row[4]  = a2[1]; row[6]  = a2[2];
                row[8]  = s2[0]; row[10] = s2[1]; row[12] = s2[2];
                row[14] = s2[3]; row[16] = s2[4];
            }
        }
        __syncwarp();

        // ---- post mixes ----
        {
            unsigned long long accI[2][2] = {};
            unsigned long long accA[3][2][2] = {};
            pass_IA(smWI_b, smWA_b, cp, lane, accI, accA);
            #pragma unroll
            for (int h = 0; h < 2; ++h)
                #pragma unroll
                for (int n = 0; n < 2; ++n) {
                    yi[h][n] = sum2(accI[h][n]);
                    #pragma unroll
                    for (int k = 0; k < 3; ++k) ya[k][h][n] = sum2(accA[k][h][n]);
                }
        }
        {
            unsigned long long accS[5][2][2] = {};
            pass_S(smWS_b, cp, lane, accS);
            #pragma unroll
            for (int h = 0; h < 2; ++h)
                #pragma unroll
                for (int n = 0; n < 2; ++n)
                    #pragma unroll
                    for (int k = 0; k < 5; ++k) ys[k][h][n] = sum2(accS[k][h][n]);
        }
        __syncwarp();

        // ---- output: O = Y2 + Y2@Y2, stage per node, store coalesced ----
        #pragma unroll
        for (int n = 0; n < 2; ++n) {
            int node = n0 + n;
            #pragma unroll
            for (int h = 0; h < 2; ++h) {
                int c = lane + 32 * h;
                float av[3] = {ya[0][h][n], ya[1][h][n], ya[2][h][n]};
                float sv[5] = {ys[0][h][n], ys[1][h][n], ys[2][h][n],
                               ys[3][h][n], ys[4][h][n]};
                float Y2[9];
                build9(yi[h][n], av, sv, Y2);
                float* od = xs + c * 9;
                #pragma unroll
                for (int i = 0; i < 3; ++i)
                    #pragma unroll
                    for (int jj = 0; jj < 3; ++jj) {
                        float acc = Y2[i * 3 + jj];
                        #pragma unroll
                        for (int k = 0; k < 3; ++k)
                            acc += Y2[i * 3 + k] * Y2[k * 3 + jj];
                        od[i * 3 + jj] = acc;
                    }
            }
            __syncwarp();
            if (node < N) {
                float4* dst = (float4*)(out + (size_t)node * 576);
                const float4* src = (const float4*)xs;
                #pragma unroll
                for (int i = 0; i < 5; ++i) {
                    int idx = lane + 32 * i;
                    if (idx < 144) dst[idx] = src[idx];
                }
            }
            __syncwarp();
        }
    }
}

// ---------------------------------------------------------------------------
extern "C" void kernel_launch(void* const* d_in, const int* in_sizes, int n_in,
                              void* d_out, int out_size)
{
    const float* X    = (const float*)d_in[0];
    const float* dist = (const float*)d_in[1];
    const int*   nb   = (const int*)d_in[2];
    const float* WIa  = (const float*)d_in[3];
    const float* WAa  = (const float*)d_in[4];
    const float* WSa  = (const float*)d_in[5];
    const float* WIb  = (const float*)d_in[6];
    const float* WAb  = (const float*)d_in[7];
    const float* WSb  = (const float*)d_in[8];
    const float* Wd   = (const float*)d_in[9];
    const float* bd   = (const float*)d_in[10];
    float* out = (float*)d_out;

    int N = in_sizes[0] / 576;
    int E = in_sizes[1];

    void* phi_ptr = nullptr;
    void* env_ptr = nullptr;
    cudaGetSymbolAddress(&phi_ptr, g_PHI);
    cudaGetSymbolAddress(&env_ptr, g_ENV);
    cudaMemsetAsync(phi_ptr, 0, sizeof(float) * (size_t)N * 32, 0);
    cudaMemsetAsync(env_ptr, 0, sizeof(float) * (size_t)N, 0);

    double e5    = exp(-5.0);
    double delta = (1.0 - e5) / 31.0;
    double bb    = (2.0 / 32.0) * (1.0 - e5);
    double beta  = 1.0 / (bb * bb);
    float  c2    = (float)(2.0 * beta * delta);
    float  qf    = (float)exp(-2.0 * beta * delta * delta);

    edge_kernel<<<(E + 255) / 256, 256>>>(dist, nb, E,
        (float)e5, (float)delta, (float)(1.0 / delta), (float)beta, c2, qf);
    coeff_kernel<<<N, 192>>>(Wd, bd, N);

    static int smem_set = 0;
    if (!smem_set) {
        cudaFuncSetAttribute(node_kernel,
                             cudaFuncAttributeMaxDynamicSharedMemorySize,
                             SMEM_FLOATS * sizeof(float));
        smem_set = 1;
    }
    node_kernel<<<148, 512, SMEM_FLOATS * sizeof(float)>>>(
        X, WIa, WAa, WSa, WIb, WAb, WSb, out, N);
}